// round 2
// baseline (speedup 1.0000x reference)
#include <cuda_runtime.h>
#include <cstdint>
#include <cstddef>

#define TB        128   // rows per block
#define NTHREADS  512
#define HID       128
#define IN_DIM    32
#define BATCH     131072

// ---------------- packed f32x2 helpers (Blackwell sm_100+) ----------------
__device__ __forceinline__ unsigned long long pk2(float lo, float hi) {
    unsigned long long r;
    asm("mov.b64 %0, {%1, %2};" : "=l"(r) : "f"(lo), "f"(hi));
    return r;
}
__device__ __forceinline__ unsigned long long fma2(unsigned long long a,
                                                   unsigned long long b,
                                                   unsigned long long c) {
    unsigned long long d;
    asm("fma.rn.f32x2 %0, %1, %2, %3;" : "=l"(d) : "l"(a), "l"(b), "l"(c));
    return d;
}
__device__ __forceinline__ float2 upk2(unsigned long long v) {
    float2 f;
    asm("mov.b64 {%0, %1}, %2;" : "=f"(f.x), "=f"(f.y) : "l"(v));
    return f;
}

// ---------------- shared memory layout (230,436 B) ----------------
struct Smem {
    float bufA[HID * TB];      // 64 KB  activations ping
    float bufB[HID * TB];      // 64 KB  activations pong
    float W1[HID * HID];       // 64 KB
    float W0[HID * IN_DIM];    // 16 KB
    union {
        float Xt[IN_DIM * TB]; // 16 KB  (input transposed; dead after layer 1)
        float W2[9 * HID];     // 4.5 KB (loaded after layer 1)
    } u;
    float b0[HID];
    float b1[HID];
    float b2[9];
};

// ---------------- 3x3 expm (scaling & squaring + Horner Taylor-10) --------
__device__ __forceinline__ void mm3(const float* A, const float* B, float* C) {
#pragma unroll
    for (int i = 0; i < 3; i++)
#pragma unroll
        for (int j = 0; j < 3; j++)
            C[3 * i + j] = fmaf(A[3 * i + 0], B[0 + j],
                           fmaf(A[3 * i + 1], B[3 + j],
                                A[3 * i + 2] * B[6 + j]));
}

__device__ void expm3(const float* A, float* E) {
    // inf-norm
    float n = 0.f;
#pragma unroll
    for (int i = 0; i < 3; i++) {
        float rs = fabsf(A[3 * i]) + fabsf(A[3 * i + 1]) + fabsf(A[3 * i + 2]);
        n = fmaxf(n, rs);
    }
    int s = 0;
    if (n > 0.5f) {
        s = (int)ceilf(log2f(n)) + 1;
        if (s < 0) s = 0;
    }
    float sc = ldexpf(1.f, -s);
    float As[9], T[9], M[9];
#pragma unroll
    for (int i = 0; i < 9; i++) {
        As[i] = A[i] * sc;
        T[i] = (i == 0 || i == 4 || i == 8) ? 1.f : 0.f;
    }
    // Horner: exp(X) = I + X(I + X/2(I + X/3(... (I + X/10) ...)))
#pragma unroll
    for (int k = 10; k >= 1; --k) {
        mm3(As, T, M);
        float inv = 1.f / (float)k;
#pragma unroll
        for (int i = 0; i < 9; i++)
            T[i] = ((i == 0 || i == 4 || i == 8) ? 1.f : 0.f) + M[i] * inv;
    }
    for (int q = 0; q < s; q++) {
        mm3(T, T, M);
#pragma unroll
        for (int i = 0; i < 9; i++) T[i] = M[i];
    }
#pragma unroll
    for (int i = 0; i < 9; i++) E[i] = T[i];
}

// ---------------- one hidden layer: src[K][TB] -> relu(W*src+b) -> dst[HID][TB]
// warp w handles 8 output neurons j = 8w..8w+7; lane handles rows 4*lane..4*lane+3
// (two f32x2 row pairs). Weight reads are warp-uniform broadcast LDS.128.
template <int K>
__device__ __forceinline__ void mlp_layer(const float* __restrict__ W,     // [HID][K]
                                          const float* __restrict__ bias,  // [HID]
                                          const float* __restrict__ src,   // [K][TB]
                                          float* __restrict__ dst,         // [HID][TB]
                                          int warp, int lane) {
    const int jbase = warp * 8;
    unsigned long long acc[8][2];
#pragma unroll
    for (int jj = 0; jj < 8; jj++) { acc[jj][0] = 0ull; acc[jj][1] = 0ull; }

#pragma unroll 2
    for (int k4 = 0; k4 < K; k4 += 4) {
        unsigned long long p[4][2];
#pragma unroll
        for (int i = 0; i < 4; i++) {
            float4 a = *(const float4*)(src + (k4 + i) * TB + lane * 4);
            p[i][0] = pk2(a.x, a.y);
            p[i][1] = pk2(a.z, a.w);
        }
#pragma unroll
        for (int jj = 0; jj < 8; jj++) {
            float4 w4 = *(const float4*)(W + (jbase + jj) * K + k4);
            unsigned long long wp;
            wp = pk2(w4.x, w4.x);
            acc[jj][0] = fma2(p[0][0], wp, acc[jj][0]);
            acc[jj][1] = fma2(p[0][1], wp, acc[jj][1]);
            wp = pk2(w4.y, w4.y);
            acc[jj][0] = fma2(p[1][0], wp, acc[jj][0]);
            acc[jj][1] = fma2(p[1][1], wp, acc[jj][1]);
            wp = pk2(w4.z, w4.z);
            acc[jj][0] = fma2(p[2][0], wp, acc[jj][0]);
            acc[jj][1] = fma2(p[2][1], wp, acc[jj][1]);
            wp = pk2(w4.w, w4.w);
            acc[jj][0] = fma2(p[3][0], wp, acc[jj][0]);
            acc[jj][1] = fma2(p[3][1], wp, acc[jj][1]);
        }
    }

#pragma unroll
    for (int jj = 0; jj < 8; jj++) {
        float b = bias[jbase + jj];
        float2 v0 = upk2(acc[jj][0]);
        float2 v1 = upk2(acc[jj][1]);
        float4 o;
        o.x = fmaxf(v0.x + b, 0.f);
        o.y = fmaxf(v0.y + b, 0.f);
        o.z = fmaxf(v1.x + b, 0.f);
        o.w = fmaxf(v1.y + b, 0.f);
        *(float4*)(dst + (jbase + jj) * TB + lane * 4) = o;
    }
}

// ---------------- main kernel: one MLP branch (rot with expm, or trz) -----
template <int OUT, bool EXPM, int COLOFF, int OUTOFF>
__global__ __launch_bounds__(NTHREADS, 1)
void mlp_kernel(const float* __restrict__ y,
                const float* __restrict__ w0, const float* __restrict__ b0,
                const float* __restrict__ w1, const float* __restrict__ b1,
                const float* __restrict__ w2, const float* __restrict__ b2,
                float* __restrict__ out) {
    extern __shared__ char smem_raw[];
    Smem& S = *reinterpret_cast<Smem*>(smem_raw);
    const int t = threadIdx.x;
    const int warp = t >> 5;
    const int lane = t & 31;
    const int r0 = blockIdx.x * TB;

    // ---- stage input transposed: y[(r0+r)*64 + COLOFF + c] -> Xt[c*TB + r]
#pragma unroll
    for (int pass = 0; pass < TB / (NTHREADS / 8); ++pass) {  // 2 passes
        int c4 = t & 7;
        int r = (t >> 3) + pass * (NTHREADS / 8);
        float4 v = *(const float4*)(y + (size_t)(r0 + r) * 64 + COLOFF + c4 * 4);
        S.u.Xt[(c4 * 4 + 0) * TB + r] = v.x;
        S.u.Xt[(c4 * 4 + 1) * TB + r] = v.y;
        S.u.Xt[(c4 * 4 + 2) * TB + r] = v.z;
        S.u.Xt[(c4 * 4 + 3) * TB + r] = v.w;
    }
    // ---- stage weights / biases (coalesced)
    for (int i = t; i < HID * IN_DIM / 4; i += NTHREADS)
        ((float4*)S.W0)[i] = ((const float4*)w0)[i];
    for (int i = t; i < HID * HID / 4; i += NTHREADS)
        ((float4*)S.W1)[i] = ((const float4*)w1)[i];
    if (t < HID) S.b0[t] = b0[t];
    else if (t < 2 * HID) S.b1[t - HID] = b1[t - HID];
    else if (t < 2 * HID + OUT) S.b2[t - 2 * HID] = b2[t - 2 * HID];
    __syncthreads();

    // ---- layer 1: Xt[32][TB] -> bufA[128][TB]
    mlp_layer<IN_DIM>(S.W0, S.b0, S.u.Xt, S.bufA, warp, lane);
    __syncthreads();

    // ---- Xt now dead: load W2 into the union
    for (int i = t; i < OUT * HID / 4; i += NTHREADS)
        ((float4*)S.u.W2)[i] = ((const float4*)w2)[i];

    // ---- layer 2: bufA -> bufB
    mlp_layer<HID>(S.W1, S.b1, S.bufA, S.bufB, warp, lane);
    __syncthreads();

    // ---- layer 3: OUT outputs per row, 4-way k-split, partials into bufA
    {
        const int p = t >> 7;        // 0..3 (constant within a warp)
        const int r = t & (TB - 1);  // row
        float o[OUT];
#pragma unroll
        for (int oo = 0; oo < OUT; oo++) o[oo] = 0.f;
        const int k0 = p * (HID / 4);
#pragma unroll 4
        for (int k = k0; k < k0 + HID / 4; ++k) {
            float a = S.bufB[k * TB + r];
#pragma unroll
            for (int oo = 0; oo < OUT; oo++)
                o[oo] = fmaf(S.u.W2[oo * HID + k], a, o[oo]);
        }
        float* scr = S.bufA;  // free during layer 3
#pragma unroll
        for (int oo = 0; oo < OUT; oo++)
            scr[(p * TB + r) * 12 + oo] = o[oo];
    }
    __syncthreads();

    // ---- reduce partials, expm (rot branch), write output
    if (t < TB) {
        const int r = t;
        const float* scr = S.bufA;
        float om[OUT];
#pragma unroll
        for (int oo = 0; oo < OUT; oo++)
            om[oo] = S.b2[oo]
                   + scr[(0 * TB + r) * 12 + oo] + scr[(1 * TB + r) * 12 + oo]
                   + scr[(2 * TB + r) * 12 + oo] + scr[(3 * TB + r) * 12 + oo];
        float* orow = out + (size_t)(r0 + r) * 12 + OUTOFF;
        if constexpr (EXPM) {
            float E[9];
            expm3(om, E);
#pragma unroll
            for (int i = 0; i < 9; i++) orow[i] = E[i];
        } else {
#pragma unroll
            for (int oo = 0; oo < OUT; oo++) orow[oo] = om[oo];
        }
    }
}

// ---------------- launch ----------------
extern "C" void kernel_launch(void* const* d_in, const int* in_sizes, int n_in,
                              void* d_out, int out_size) {
    const float* y   = (const float*)d_in[0];
    const float* ow0 = (const float*)d_in[1];
    const float* ob0 = (const float*)d_in[2];
    const float* ow1 = (const float*)d_in[3];
    const float* ob1 = (const float*)d_in[4];
    const float* ow2 = (const float*)d_in[5];
    const float* ob2 = (const float*)d_in[6];
    const float* tw0 = (const float*)d_in[7];
    const float* tb0 = (const float*)d_in[8];
    const float* tw1 = (const float*)d_in[9];
    const float* tb1 = (const float*)d_in[10];
    const float* tw2 = (const float*)d_in[11];
    const float* tb2 = (const float*)d_in[12];
    float* out = (float*)d_out;

    const size_t smem = sizeof(Smem);
    cudaFuncSetAttribute(mlp_kernel<9, true, 0, 0>,
                         cudaFuncAttributeMaxDynamicSharedMemorySize, (int)smem);
    cudaFuncSetAttribute(mlp_kernel<3, false, 32, 9>,
                         cudaFuncAttributeMaxDynamicSharedMemorySize, (int)smem);

    dim3 grid(BATCH / TB);
    mlp_kernel<9, true, 0, 0><<<grid, NTHREADS, smem>>>(
        y, ow0, ob0, ow1, ob1, ow2, ob2, out);
    mlp_kernel<3, false, 32, 9><<<grid, NTHREADS, smem>>>(
        y, tw0, tb0, tw1, tb1, tw2, tb2, out);
}

// round 4
// speedup vs baseline: 2.7600x; 2.7600x over previous
#include <cuda_runtime.h>
#include <cuda_bf16.h>
#include <cstdint>
#include <cstddef>

#define NTHREADS 256
#define GRID     148
#define TB       128
#define NTILES   1024   // 131072 / 128

// ---------------- smem layout (bytes) ----------------
// padded K-major bf16 tiles: row stride = K*2 + 16 bytes (conflict-free ldmatrix)
#define ST32B  80     // K=32 rows: 32*2+16
#define ST128B 272    // K=128 rows: 128*2+16
#define S_XH   0                    // x hi  [128 rows x 80B]
#define S_XL   10240
#define S_W0H  20480                // W0 [128 x 80B]
#define S_W0L  30720
#define S_W1H  40960                // W1 [128 x 272B]
#define S_W1L  75776
#define S_W2H  110592               // W2 [16 x 272B]  (rows >= OUT zero)
#define S_W2L  114944
#define S_B0   119296               // 128 f32
#define S_B1   119808
#define S_B2   120320               // 16 f32
#define S_OUT  120448               // [128 rows x 16 f32] staging
#define SMEM_TOTAL 128640

// ---------------- PTX helpers ----------------
__device__ __forceinline__ uint32_t cvta_s(const void* p) {
    uint32_t a;
    asm("{ .reg .u64 t; cvta.to.shared.u64 t, %1; cvt.u32.u64 %0, t; }"
        : "=r"(a) : "l"(p));
    return a;
}
__device__ __forceinline__ void ldsm4(uint32_t* r, uint32_t addr) {
    asm volatile("ldmatrix.sync.aligned.m8n8.x4.shared.b16 {%0,%1,%2,%3}, [%4];"
                 : "=r"(r[0]), "=r"(r[1]), "=r"(r[2]), "=r"(r[3]) : "r"(addr));
}
__device__ __forceinline__ void mma16816(float* d, const uint32_t* a,
                                         uint32_t b0, uint32_t b1) {
    asm volatile(
        "mma.sync.aligned.m16n8k16.row.col.f32.bf16.bf16.f32 "
        "{%0,%1,%2,%3}, {%4,%5,%6,%7}, {%8,%9}, {%0,%1,%2,%3};"
        : "+f"(d[0]), "+f"(d[1]), "+f"(d[2]), "+f"(d[3])
        : "r"(a[0]), "r"(a[1]), "r"(a[2]), "r"(a[3]), "r"(b0), "r"(b1));
}
__device__ __forceinline__ uint32_t pkbf(float lo, float hi) {  // low half = lo
    uint32_t r;
    asm("cvt.rn.bf16x2.f32 %0, %1, %2;" : "=r"(r) : "f"(hi), "f"(lo));
    return r;
}
__device__ __forceinline__ float bf_lo(uint32_t u) { return __uint_as_float(u << 16); }
__device__ __forceinline__ float bf_hi(uint32_t u) { return __uint_as_float(u & 0xFFFF0000u); }

// ---------------- 3x3 expm (validated round 1/2) ----------------
__device__ __forceinline__ void mm3(const float* A, const float* B, float* C) {
#pragma unroll
    for (int i = 0; i < 3; i++)
#pragma unroll
        for (int j = 0; j < 3; j++)
            C[3 * i + j] = fmaf(A[3 * i + 0], B[0 + j],
                           fmaf(A[3 * i + 1], B[3 + j],
                                A[3 * i + 2] * B[6 + j]));
}
__device__ void expm3(const float* A, float* E) {
    float n = 0.f;
#pragma unroll
    for (int i = 0; i < 3; i++) {
        float rs = fabsf(A[3 * i]) + fabsf(A[3 * i + 1]) + fabsf(A[3 * i + 2]);
        n = fmaxf(n, rs);
    }
    int s = 0;
    if (n > 0.5f) { s = (int)ceilf(log2f(n)) + 1; if (s < 0) s = 0; }
    float sc = ldexpf(1.f, -s);
    float As[9], T[9], M[9];
#pragma unroll
    for (int i = 0; i < 9; i++) {
        As[i] = A[i] * sc;
        T[i] = (i == 0 || i == 4 || i == 8) ? 1.f : 0.f;
    }
#pragma unroll
    for (int k = 10; k >= 1; --k) {
        mm3(As, T, M);
        float inv = 1.f / (float)k;
#pragma unroll
        for (int i = 0; i < 9; i++)
            T[i] = ((i == 0 || i == 4 || i == 8) ? 1.f : 0.f) + M[i] * inv;
    }
    for (int q = 0; q < s; q++) {
        mm3(T, T, M);
#pragma unroll
        for (int i = 0; i < 9; i++) T[i] = M[i];
    }
#pragma unroll
    for (int i = 0; i < 9; i++) E[i] = T[i];
}

// ---------------- split fp32 -> bf16 hi/lo, 4 consecutive elems ----------
__device__ __forceinline__ void split_store4(char* sm, uint32_t off_hi, uint32_t off_lo,
                                             float4 v) {
    uint32_t h01 = pkbf(v.x, v.y);
    uint32_t h23 = pkbf(v.z, v.w);
    float l0 = v.x - bf_lo(h01), l1 = v.y - bf_hi(h01);
    float l2 = v.z - bf_lo(h23), l3 = v.w - bf_hi(h23);
    *(uint2*)(sm + off_hi) = make_uint2(h01, h23);
    *(uint2*)(sm + off_lo) = make_uint2(pkbf(l0, l1), pkbf(l2, l3));
}

// ---------------- weight conversion: fp32 [R x C] -> padded split bf16 ---
__device__ void conv_w(const float* __restrict__ src, int R, int C, int RP,
                       int strideB, char* sm, uint32_t dhi, uint32_t dlo, int tid) {
    const int c4n = C / 4;
    const int tot = RP * c4n;
    for (int i = tid; i < tot; i += NTHREADS) {
        int row = i / c4n, c4 = i - row * c4n;
        float4 v = (row < R) ? *(const float4*)(src + (size_t)row * C + c4 * 4)
                             : make_float4(0.f, 0.f, 0.f, 0.f);
        uint32_t o = (uint32_t)(row * strideB + c4 * 8);
        split_store4(sm, dhi + o, dlo + o, v);
    }
}

// ---------------- GEMM layer: D[NT16*8] += (Ah+Al) x (Bh+Bl) -------------
template <int KT, int NT16, int STRIDEB>
__device__ __forceinline__ void gemm(uint32_t bh_base, uint32_t bl_base,
                                     const uint32_t* ah, const uint32_t* al,
                                     float* d, int n_in, int k_in) {
#pragma unroll
    for (int nt = 0; nt < NT16; nt++) {
#pragma unroll
        for (int kt = 0; kt < KT; kt++) {
            uint32_t off = (uint32_t)((nt * 16 + n_in) * STRIDEB + kt * 32 + k_in * 2);
            uint32_t bh[4], bl[4];
            ldsm4(bh, bh_base + off);
            ldsm4(bl, bl_base + off);
            float* d0 = d + nt * 8;
            float* d1 = d + nt * 8 + 4;
            mma16816(d0, ah + kt * 4, bh[0], bh[1]);
            mma16816(d1, ah + kt * 4, bh[2], bh[3]);
            mma16816(d0, al + kt * 4, bh[0], bh[1]);
            mma16816(d1, al + kt * 4, bh[2], bh[3]);
            mma16816(d0, ah + kt * 4, bl[0], bl[1]);
            mma16816(d1, ah + kt * 4, bl[2], bl[3]);
        }
    }
}

// ---------------- epilogue: D[64] + bias -> relu -> split A frags --------
__device__ __forceinline__ void epi128(const float* d, const char* sm, uint32_t bias_off,
                                       uint32_t* ah, uint32_t* al, int lane) {
    const int cb = (lane & 3) * 2;
#pragma unroll
    for (int tj = 0; tj < 16; tj++) {
        float2 bb = *(const float2*)(sm + bias_off + (tj * 8 + cb) * 4);
        float v0 = fmaxf(d[tj * 4 + 0] + bb.x, 0.f);
        float v1 = fmaxf(d[tj * 4 + 1] + bb.y, 0.f);
        float v2 = fmaxf(d[tj * 4 + 2] + bb.x, 0.f);
        float v3 = fmaxf(d[tj * 4 + 3] + bb.y, 0.f);
        uint32_t h01 = pkbf(v0, v1);
        uint32_t h23 = pkbf(v2, v3);
        float l0 = v0 - bf_lo(h01), l1 = v1 - bf_hi(h01);
        float l2 = v2 - bf_lo(h23), l3 = v3 - bf_hi(h23);
        const int idx = (tj >> 1) * 4 + (tj & 1) * 2;
        ah[idx + 0] = h01;
        ah[idx + 1] = h23;
        al[idx + 0] = pkbf(l0, l1);
        al[idx + 1] = pkbf(l2, l3);
    }
}

// ---------------- main fused kernel ----------------
__global__ __launch_bounds__(NTHREADS, 1)
void fused_kernel(const float* __restrict__ y,
                  const float* __restrict__ ow0, const float* __restrict__ ob0,
                  const float* __restrict__ ow1, const float* __restrict__ ob1,
                  const float* __restrict__ ow2, const float* __restrict__ ob2,
                  const float* __restrict__ tw0, const float* __restrict__ tb0,
                  const float* __restrict__ tw1, const float* __restrict__ tb1,
                  const float* __restrict__ tw2, const float* __restrict__ tb2,
                  float* __restrict__ out) {
    extern __shared__ char sm[];
    const uint32_t smb = cvta_s(sm);
    const int tid = threadIdx.x;
    const int warp = tid >> 5;
    const int lane = tid & 31;

    // ldmatrix lane geometry
    const int lt = lane >> 3, lr = lane & 7;
    const int b_n = (lt >> 1) * 8 + lr;   // B x4: n row within n16 group
    const int b_k = (lt & 1) * 8;         // B x4: k offset within k16
    const int a_m = (lt & 1) * 8 + lr;    // A x4: m row within m16
    const int a_k = (lt >> 1) * 8;        // A x4: k offset within k16

    for (int br = 0; br < 2; br++) {
        const float* w0 = br ? tw0 : ow0;
        const float* w1 = br ? tw1 : ow1;
        const float* w2 = br ? tw2 : ow2;
        const float* b0 = br ? tb0 : ob0;
        const float* b1 = br ? tb1 : ob1;
        const float* b2 = br ? tb2 : ob2;
        const int coloff = br ? 32 : 0;
        const int OUTN = br ? 3 : 9;

        __syncthreads();  // previous branch fully done before weight overwrite
        conv_w(w0, 128, 32, 128, ST32B, sm, S_W0H, S_W0L, tid);
        conv_w(w1, 128, 128, 128, ST128B, sm, S_W1H, S_W1L, tid);
        conv_w(w2, OUTN, 128, 16, ST128B, sm, S_W2H, S_W2L, tid);
        if (tid < 128) ((float*)(sm + S_B0))[tid] = b0[tid];
        else if (tid < 256) ((float*)(sm + S_B1))[tid - 128] = b1[tid - 128];
        if (tid < 16) ((float*)(sm + S_B2))[tid] = (tid < OUTN) ? b2[tid] : 0.f;
        __syncthreads();

        for (int t = blockIdx.x; t < NTILES; t += GRID) {
            const int r0 = t * TB;

            // ---- stage x tile: [128 x 32] split bf16, padded rows ----
#pragma unroll
            for (int pass = 0; pass < 4; pass++) {
                int i = tid + pass * NTHREADS;        // 1024 float4s
                int row = i >> 3, c4 = i & 7;
                float4 v = *(const float4*)(y + (size_t)(r0 + row) * 64 + coloff + c4 * 4);
                uint32_t o = (uint32_t)(row * ST32B + c4 * 8);
                split_store4(sm, S_XH + o, S_XL + o, v);
            }
            __syncthreads();

            // ---- load x A-fragments ----
            uint32_t axh[8], axl[8];
#pragma unroll
            for (int kt = 0; kt < 2; kt++) {
                uint32_t o = (uint32_t)((warp * 16 + a_m) * ST32B + (kt * 16 + a_k) * 2);
                ldsm4(axh + kt * 4, smb + S_XH + o);
                ldsm4(axl + kt * 4, smb + S_XL + o);
            }

            // ---- layer 1: [16 x 32] x W0^T -> D[16 x 128] ----
            float d[64];
#pragma unroll
            for (int i = 0; i < 64; i++) d[i] = 0.f;
            gemm<2, 8, ST32B>(smb + S_W0H, smb + S_W0L, axh, axl, d, b_n, b_k);

            uint32_t acth[32], actl[32];
            epi128(d, sm, S_B0, acth, actl, lane);

            // ---- layer 2: [16 x 128] x W1^T -> D[16 x 128] ----
#pragma unroll
            for (int i = 0; i < 64; i++) d[i] = 0.f;
            gemm<8, 8, ST128B>(smb + S_W1H, smb + S_W1L, acth, actl, d, b_n, b_k);
            epi128(d, sm, S_B1, acth, actl, lane);

            // ---- layer 3: [16 x 128] x W2^T -> D3[16 x 16] ----
            float d3[8];
#pragma unroll
            for (int i = 0; i < 8; i++) d3[i] = 0.f;
            gemm<8, 1, ST128B>(smb + S_W2H, smb + S_W2L, acth, actl, d3, b_n, b_k);

            // ---- stage D3 to smem [row][16] ----
            {
                char* ob = sm + S_OUT + (size_t)(warp * 16) * 64;
                const int rlo = lane >> 2;
                const int c = (lane & 3) * 2;
#pragma unroll
                for (int tj = 0; tj < 2; tj++) {
                    *(float2*)(ob + rlo * 64 + (tj * 8 + c) * 4) =
                        make_float2(d3[tj * 4 + 0], d3[tj * 4 + 1]);
                    *(float2*)(ob + (rlo + 8) * 64 + (tj * 8 + c) * 4) =
                        make_float2(d3[tj * 4 + 2], d3[tj * 4 + 3]);
                }
            }
            __syncthreads();

            // ---- bias + expm + write ----
            if (tid < TB) {
                const float* orow_s = (const float*)(sm + S_OUT) + tid * 16;
                const float* b2s = (const float*)(sm + S_B2);
                float* og = out + (size_t)(r0 + tid) * 12 + (br ? 9 : 0);
                if (br == 0) {
                    float om[9], E[9];
#pragma unroll
                    for (int o = 0; o < 9; o++) om[o] = orow_s[o] + b2s[o];
                    expm3(om, E);
#pragma unroll
                    for (int o = 0; o < 9; o++) og[o] = E[o];
                } else {
#pragma unroll
                    for (int o = 0; o < 3; o++) og[o] = orow_s[o] + b2s[o];
                }
            }
            __syncthreads();
        }
    }
}

// ---------------- launch ----------------
extern "C" void kernel_launch(void* const* d_in, const int* in_sizes, int n_in,
                              void* d_out, int out_size) {
    const float* y   = (const float*)d_in[0];
    const float* ow0 = (const float*)d_in[1];
    const float* ob0 = (const float*)d_in[2];
    const float* ow1 = (const float*)d_in[3];
    const float* ob1 = (const float*)d_in[4];
    const float* ow2 = (const float*)d_in[5];
    const float* ob2 = (const float*)d_in[6];
    const float* tw0 = (const float*)d_in[7];
    const float* tb0 = (const float*)d_in[8];
    const float* tw1 = (const float*)d_in[9];
    const float* tb1 = (const float*)d_in[10];
    const float* tw2 = (const float*)d_in[11];
    const float* tb2 = (const float*)d_in[12];
    float* out = (float*)d_out;

    cudaFuncSetAttribute(fused_kernel,
                         cudaFuncAttributeMaxDynamicSharedMemorySize, SMEM_TOTAL);
    fused_kernel<<<GRID, NTHREADS, SMEM_TOTAL>>>(
        y, ow0, ob0, ow1, ob1, ow2, ob2, tw0, tb0, tw1, tb1, tw2, tb2, out);
}